// round 5
// baseline (speedup 1.0000x reference)
#include <cuda_runtime.h>

#define H 256
#define D 8
#define BN_EPS 1e-5f

typedef unsigned long long u64;

// ---------------- packed f32x2 helpers ----------------
__device__ __forceinline__ u64 ffma2(u64 a, u64 b, u64 c) {
    u64 d; asm("fma.rn.f32x2 %0, %1, %2, %3;" : "=l"(d) : "l"(a), "l"(b), "l"(c)); return d;
}
__device__ __forceinline__ u64 fadd2(u64 a, u64 b) {
    u64 d; asm("add.rn.f32x2 %0, %1, %2;" : "=l"(d) : "l"(a), "l"(b)); return d;
}
__device__ __forceinline__ u64 pack2(float lo, float hi) {
    u64 d; asm("mov.b64 %0, {%1, %2};" : "=l"(d) : "f"(lo), "f"(hi)); return d;
}
__device__ __forceinline__ float2 unpack2(u64 v) {
    float lo, hi; asm("mov.b64 {%0, %1}, %2;" : "=f"(lo), "=f"(hi) : "l"(v));
    return make_float2(lo, hi);
}
__device__ __forceinline__ u64 abs2(u64 v) {
    u64 d; asm("and.b64 %0, %1, 0x7FFFFFFF7FFFFFFF;" : "=l"(d) : "l"(v)); return d;
}
// relu2x: returns 2*relu per lane (q + |q|)
__device__ __forceinline__ u64 relu2x(u64 q) { return fadd2(q, abs2(q)); }

// ---------------- device scratch (static, allocation-free) ----------------
__device__ float g_P [H * D];   // Wo @ Wp
__device__ float g_T2[H * D];   // Wv @ P
__device__ float g_M [H * D];   // W2 @ T2
__device__ float g_c [D];       // folded bias chain
__device__ float g_sum  [H];    // per-column sum of r = 2h
__device__ float g_sumsq[H];    // per-column sum of r^2 = 4h^2
__device__ float g_Ms[H * D];   // 0.25 * diag(s) @ M
__device__ float g_c8[D];       // 0.5 * (t @ M + c)

// ---------------- single fold kernel: P -> T2 -> M, c ; zero stats ----------------
__global__ void __launch_bounds__(256) k_fold_all(
    const float* __restrict__ Wo, const float* __restrict__ Wp,
    const float* __restrict__ Wv,
    const float* __restrict__ W2, const float* __restrict__ b2,
    const float* __restrict__ bv, const float* __restrict__ bo,
    const float* __restrict__ bp) {
    const int t = threadIdx.x;
    // phase 1: P = Wo @ Wp
    for (int idx = t; idx < H * D; idx += 256) {
        int i = idx >> 3, d = idx & 7;
        float acc = 0.f;
#pragma unroll 8
        for (int k = 0; k < H; k++) acc = fmaf(Wo[i * H + k], Wp[k * D + d], acc);
        g_P[idx] = acc;
    }
    g_sum[t] = 0.f; g_sumsq[t] = 0.f;
    __syncthreads();
    // phase 2: T2 = Wv @ P
    for (int idx = t; idx < H * D; idx += 256) {
        int i = idx >> 3, d = idx & 7;
        float acc = 0.f;
#pragma unroll 8
        for (int k = 0; k < H; k++) acc = fmaf(Wv[i * H + k], g_P[k * D + d], acc);
        g_T2[idx] = acc;
    }
    __syncthreads();
    // phase 3: M = W2 @ T2 ; c = b2@T2 + bv@P + bo@Wp + bp
    for (int idx = t; idx < H * D; idx += 256) {
        int i = idx >> 3, d = idx & 7;
        float acc = 0.f;
#pragma unroll 8
        for (int k = 0; k < H; k++) acc = fmaf(W2[i * H + k], g_T2[k * D + d], acc);
        g_M[idx] = acc;
    }
    if (t < D) {
        float c = bp[t];
        for (int k = 0; k < H; k++) {
            c = fmaf(b2[k], g_T2[k * D + t], c);
            c = fmaf(bv[k], g_P [k * D + t], c);
            c = fmaf(bo[k], Wp  [k * D + t], c);
        }
        g_c[t] = c;
    }
}

// ---------------- pass 1: batch statistics of h = relu(nc@W1 + b1) ----------------
// 128 threads/block; thread owns cols t and t+128 (halves broadcast LDS per FMA).
// Double-buffered tile staging: prefetch gathers -> compute -> STS -> bar.
__global__ void __launch_bounds__(128) k_pass1(
    const float* __restrict__ nf, const int* __restrict__ ei,
    const float* __restrict__ W1, const float* __restrict__ b1, int E) {
    __shared__ __align__(16) float ncsT[2][8][256];   // [buf][k][edge-in-tile]
    const int t = threadIdx.x;

    u64 wA[8], wB[8];
#pragma unroll
    for (int k = 0; k < 8; k++) {
        float a = W1[k * H + t];        wA[k] = pack2(a, a);
        float b = W1[k * H + t + 128];  wB[k] = pack2(b, b);
    }
    const float bAs = b1[t], bBs = b1[t + 128];
    const u64 bA = pack2(bAs, bAs);
    const u64 bB = pack2(bBs, bBs);

    u64 sumA = pack2(0.f, 0.f), ssqA = sumA;   // col t
    u64 sumB = sumA, ssqB = sumA;              // col t+128
    const int numTiles = (E + 255) >> 8;

    // ---- stage first tile into buf 0 ----
    {
        const int base = blockIdx.x << 8;
        for (int s = 0; s < 2; s++) {
            int e = base + t + s * 128;
            if (e < E) {
                int s0 = ei[e], s1 = ei[E + e];
                const float4* a = (const float4*)(nf + (size_t)s0 * D);
                const float4* b = (const float4*)(nf + (size_t)s1 * D);
                float4 x0 = a[0], x1 = a[1], y0 = b[0], y1 = b[1];
                int c = t + s * 128;
                ncsT[0][0][c] = 0.5f * (x0.x + y0.x);
                ncsT[0][1][c] = 0.5f * (x0.y + y0.y);
                ncsT[0][2][c] = 0.5f * (x0.z + y0.z);
                ncsT[0][3][c] = 0.5f * (x0.w + y0.w);
                ncsT[0][4][c] = 0.5f * (x1.x + y1.x);
                ncsT[0][5][c] = 0.5f * (x1.y + y1.y);
                ncsT[0][6][c] = 0.5f * (x1.z + y1.z);
                ncsT[0][7][c] = 0.5f * (x1.w + y1.w);
            }
        }
    }
    __syncthreads();

    int buf = 0;
    for (int tile = blockIdx.x; tile < numTiles; tile += gridDim.x) {
        const int base = tile << 8;
        const int cnt  = min(256, E - base);
        const int nt   = tile + gridDim.x;

        // ---- prefetch next tile's gathers into registers (latency overlaps compute) ----
        float4 px0[2], px1[2], py0[2], py1[2];
        bool pv[2] = {false, false};
        if (nt < numTiles) {
            const int nbase = nt << 8;
#pragma unroll
            for (int s = 0; s < 2; s++) {
                int e = nbase + t + s * 128;
                if (e < E) {
                    pv[s] = true;
                    int s0 = ei[e], s1 = ei[E + e];
                    const float4* a = (const float4*)(nf + (size_t)s0 * D);
                    const float4* b = (const float4*)(nf + (size_t)s1 * D);
                    px0[s] = a[0]; px1[s] = a[1]; py0[s] = b[0]; py1[s] = b[1];
                }
            }
        }

        // ---- compute current buf ----
        const float (*nb)[256] = ncsT[buf];
        int e = 0;
        for (; e + 3 < cnt; e += 4) {
            u64 qA0 = bA, qA1 = bA, qB0 = bB, qB1 = bB;
#pragma unroll
            for (int k = 0; k < 8; k++) {
                ulonglong2 n = *(const ulonglong2*)&nb[k][e];
                qA0 = ffma2(n.x, wA[k], qA0);
                qA1 = ffma2(n.y, wA[k], qA1);
                qB0 = ffma2(n.x, wB[k], qB0);
                qB1 = ffma2(n.y, wB[k], qB1);
            }
            u64 rA0 = relu2x(qA0), rA1 = relu2x(qA1);
            u64 rB0 = relu2x(qB0), rB1 = relu2x(qB1);
            sumA = fadd2(sumA, rA0);     sumA = fadd2(sumA, rA1);
            ssqA = ffma2(rA0, rA0, ssqA); ssqA = ffma2(rA1, rA1, ssqA);
            sumB = fadd2(sumB, rB0);     sumB = fadd2(sumB, rB1);
            ssqB = ffma2(rB0, rB0, ssqB); ssqB = ffma2(rB1, rB1, ssqB);
        }
        for (; e + 1 < cnt; e += 2) {
            u64 qA0 = bA, qB0 = bB;
#pragma unroll
            for (int k = 0; k < 8; k++) {
                u64 n = *(const u64*)&nb[k][e];
                qA0 = ffma2(n, wA[k], qA0);
                qB0 = ffma2(n, wB[k], qB0);
            }
            u64 rA0 = relu2x(qA0), rB0 = relu2x(qB0);
            sumA = fadd2(sumA, rA0); ssqA = ffma2(rA0, rA0, ssqA);
            sumB = fadd2(sumB, rB0); ssqB = ffma2(rB0, rB0, ssqB);
        }
        if (e < cnt) {                      // odd tail: hi lane poisoned -> r=0
            u64 qA0 = pack2(bAs, -1e30f), qB0 = pack2(bBs, -1e30f);
#pragma unroll
            for (int k = 0; k < 8; k++) {
                u64 n = pack2(nb[k][e], 0.f);
                qA0 = ffma2(n, wA[k], qA0);
                qB0 = ffma2(n, wB[k], qB0);
            }
            u64 rA0 = relu2x(qA0), rB0 = relu2x(qB0);
            sumA = fadd2(sumA, rA0); ssqA = ffma2(rA0, rA0, ssqA);
            sumB = fadd2(sumB, rB0); ssqB = ffma2(rB0, rB0, ssqB);
        }

        // ---- store next tile into other buffer ----
        if (nt < numTiles) {
            int nbuf = buf ^ 1;
#pragma unroll
            for (int s = 0; s < 2; s++) {
                if (pv[s]) {
                    int c = t + s * 128;
                    ncsT[nbuf][0][c] = 0.5f * (px0[s].x + py0[s].x);
                    ncsT[nbuf][1][c] = 0.5f * (px0[s].y + py0[s].y);
                    ncsT[nbuf][2][c] = 0.5f * (px0[s].z + py0[s].z);
                    ncsT[nbuf][3][c] = 0.5f * (px0[s].w + py0[s].w);
                    ncsT[nbuf][4][c] = 0.5f * (px1[s].x + py1[s].x);
                    ncsT[nbuf][5][c] = 0.5f * (px1[s].y + py1[s].y);
                    ncsT[nbuf][6][c] = 0.5f * (px1[s].z + py1[s].z);
                    ncsT[nbuf][7][c] = 0.5f * (px1[s].w + py1[s].w);
                }
            }
        }
        __syncthreads();     // drains STS; guards buffer swap both directions
        buf ^= 1;
    }

    float2 sa = unpack2(sumA), qa = unpack2(ssqA);
    float2 sb = unpack2(sumB), qb = unpack2(ssqB);
    atomicAdd(&g_sum[t],         sa.x + sa.y);
    atomicAdd(&g_sumsq[t],       qa.x + qa.y);
    atomicAdd(&g_sum[t + 128],   sb.x + sb.y);
    atomicAdd(&g_sumsq[t + 128], qb.x + qb.y);
}

// ---------------- finalize: fold BN affine (+relu-doubling factors) into M ----------------
__global__ void k_finalize(const float* __restrict__ gamma,
                           const float* __restrict__ beta, float invE) {
    __shared__ float tvs[H];
    const int j = threadIdx.x;
    float mu  = 0.5f  * g_sum[j]   * invE;              // E[h]
    float eh2 = 0.25f * g_sumsq[j] * invE;              // E[h^2]
    float var = fmaf(-mu, mu, eh2);                     // biased var
    float s   = gamma[j] * rsqrtf(var + BN_EPS);
    float tv  = fmaf(-mu, s, beta[j]);
#pragma unroll
    for (int d = 0; d < D; d++) g_Ms[j * D + d] = 0.25f * s * g_M[j * D + d];
    tvs[j] = tv;
    __syncthreads();
    if (j < D) {
        float acc = g_c[j];
        for (int k = 0; k < H; k++) acc = fmaf(tvs[k], g_M[k * D + j], acc);
        g_c8[j] = 0.5f * acc;
    }
}

// ---------------- pass 2: out = ea + (r @ Ms025) + c8h,  r = 2*relu(nc@W1+b1) ----------------
// edge-owner, 3 edges/thread, 128-thread blocks; cols packed in f32x2 lane pairs.
__global__ void __launch_bounds__(128) k_pass2(
    const float* __restrict__ ea, const float* __restrict__ nf,
    const int* __restrict__ ei,
    const float* __restrict__ W1, const float* __restrict__ b1,
    float* __restrict__ out, int E) {
    __shared__ __align__(16) u64 w2p [128 * 8];   // [jp][k]  = (W1[k][2jp], W1[k][2jp+1])
    __shared__ __align__(16) u64 ms2p[128 * 8];   // [jp][d]  = (Ms[2jp][d], Ms[2jp+1][d])
    __shared__ u64 b2ps[128];                     // (b1[2jp], b1[2jp+1])
    __shared__ float c8s[D];

    const int t = threadIdx.x;
    for (int idx = t; idx < 128 * 8; idx += 128) {
        int jp = idx >> 3, k = idx & 7;
        w2p [idx] = pack2(W1[k * H + 2 * jp], W1[k * H + 2 * jp + 1]);
        ms2p[idx] = pack2(g_Ms[(2 * jp) * D + k], g_Ms[(2 * jp + 1) * D + k]);
    }
    b2ps[t] = pack2(b1[2 * t], b1[2 * t + 1]);
    if (t < D) c8s[t] = g_c8[t];
    __syncthreads();

    int eidx[3]; bool val[3];
#pragma unroll
    for (int i = 0; i < 3; i++) {
        int er = blockIdx.x * 384 + i * 128 + t;
        val[i]  = er < E;
        eidx[i] = val[i] ? er : E - 1;
    }

    // gather + duplicate-pack nc for 3 edges
    u64 nc[3][8];
#pragma unroll
    for (int i = 0; i < 3; i++) {
        const int s0 = ei[eidx[i]];
        const int s1 = ei[E + eidx[i]];
        const float4* p0 = (const float4*)(nf + (size_t)s0 * D);
        const float4* p1 = (const float4*)(nf + (size_t)s1 * D);
        float4 x0 = p0[0], x1 = p0[1], y0 = p1[0], y1 = p1[1];
        float n[8];
        n[0] = 0.5f * (x0.x + y0.x); n[1] = 0.5f * (x0.y + y0.y);
        n[2] = 0.5f * (x0.z + y0.z); n[3] = 0.5f * (x0.w + y0.w);
        n[4] = 0.5f * (x1.x + y1.x); n[5] = 0.5f * (x1.y + y1.y);
        n[6] = 0.5f * (x1.z + y1.z); n[7] = 0.5f * (x1.w + y1.w);
#pragma unroll
        for (int k = 0; k < 8; k++) nc[i][k] = pack2(n[k], n[k]);
    }

    u64 acc[3][8];
    const u64 z = pack2(0.f, 0.f);
#pragma unroll
    for (int i = 0; i < 3; i++)
#pragma unroll
        for (int d = 0; d < 8; d++) acc[i][d] = z;

#pragma unroll 1
    for (int jp = 0; jp < 128; jp++) {
        u64 w8[8];
        {
            ulonglong2 v0 = *(const ulonglong2*)&w2p[jp * 8 + 0];
            ulonglong2 v1 = *(const ulonglong2*)&w2p[jp * 8 + 2];
            ulonglong2 v2 = *(const ulonglong2*)&w2p[jp * 8 + 4];
            ulonglong2 v3 = *(const ulonglong2*)&w2p[jp * 8 + 6];
            w8[0] = v0.x; w8[1] = v0.y; w8[2] = v1.x; w8[3] = v1.y;
            w8[4] = v2.x; w8[5] = v2.y; w8[6] = v3.x; w8[7] = v3.y;
        }
        const u64 bp = b2ps[jp];
        u64 q0 = bp, q1 = bp, q2 = bp;
#pragma unroll
        for (int k = 0; k < 8; k++) {
            q0 = ffma2(nc[0][k], w8[k], q0);
            q1 = ffma2(nc[1][k], w8[k], q1);
            q2 = ffma2(nc[2][k], w8[k], q2);
        }
        u64 r0 = relu2x(q0), r1 = relu2x(q1), r2 = relu2x(q2);

        u64 m8[8];
        {
            ulonglong2 v0 = *(const ulonglong2*)&ms2p[jp * 8 + 0];
            ulonglong2 v1 = *(const ulonglong2*)&ms2p[jp * 8 + 2];
            ulonglong2 v2 = *(const ulonglong2*)&ms2p[jp * 8 + 4];
            ulonglong2 v3 = *(const ulonglong2*)&ms2p[jp * 8 + 6];
            m8[0] = v0.x; m8[1] = v0.y; m8[2] = v1.x; m8[3] = v1.y;
            m8[4] = v2.x; m8[5] = v2.y; m8[6] = v3.x; m8[7] = v3.y;
        }
#pragma unroll
        for (int d = 0; d < 8; d++) {
            acc[0][d] = ffma2(r0, m8[d], acc[0][d]);
            acc[1][d] = ffma2(r1, m8[d], acc[1][d]);
            acc[2][d] = ffma2(r2, m8[d], acc[2][d]);
        }
    }

#pragma unroll
    for (int i = 0; i < 3; i++) {
        if (!val[i]) continue;
        const float4* eap = (const float4*)(ea + (size_t)eidx[i] * D);
        float4 i0 = eap[0], i1 = eap[1];
        float o[8];
#pragma unroll
        for (int d = 0; d < 8; d++) {
            float2 p = unpack2(acc[i][d]);
            o[d] = p.x + p.y + c8s[d];
        }
        float4 o0 = make_float4(i0.x + o[0], i0.y + o[1], i0.z + o[2], i0.w + o[3]);
        float4 o1 = make_float4(i1.x + o[4], i1.y + o[5], i1.z + o[6], i1.w + o[7]);
        float4* op = (float4*)(out + (size_t)eidx[i] * D);
        op[0] = o0; op[1] = o1;
    }
}

// ---------------- launcher ----------------
extern "C" void kernel_launch(void* const* d_in, const int* in_sizes, int n_in,
                              void* d_out, int out_size) {
    const float* edge_attr     = (const float*)d_in[0];
    const float* node_features = (const float*)d_in[1];
    const int*   edge_index    = (const int*)  d_in[2];
    // d_in[3..8]: edge-encoder params — unused by the reference output
    const float* n_W1    = (const float*)d_in[9];
    const float* n_b1    = (const float*)d_in[10];
    const float* n_gamma = (const float*)d_in[11];
    const float* n_beta  = (const float*)d_in[12];
    const float* n_W2    = (const float*)d_in[13];
    const float* n_b2    = (const float*)d_in[14];
    const float* Wv      = (const float*)d_in[15];
    const float* bv      = (const float*)d_in[16];
    const float* Wo      = (const float*)d_in[17];
    const float* bo      = (const float*)d_in[18];
    const float* Wp      = (const float*)d_in[19];
    const float* bp      = (const float*)d_in[20];

    const int E = in_sizes[0] / D;
    float* out = (float*)d_out;

    k_fold_all<<<1, 256>>>(Wo, Wp, Wv, n_W2, n_b2, bv, bo, bp);
    k_pass1<<<1184, 128>>>(node_features, edge_index, n_W1, n_b1, E);
    k_finalize<<<1, 256>>>(n_gamma, n_beta, 1.0f / (float)E);
    k_pass2<<<(E + 383) / 384, 128>>>(edge_attr, node_features, edge_index,
                                      n_W1, n_b1, out, E);
}

// round 6
// speedup vs baseline: 1.5446x; 1.5446x over previous
#include <cuda_runtime.h>

#define H 256
#define D 8
#define BN_EPS 1e-5f

typedef unsigned long long u64;

// ---------------- packed f32x2 helpers ----------------
__device__ __forceinline__ u64 ffma2(u64 a, u64 b, u64 c) {
    u64 d; asm("fma.rn.f32x2 %0, %1, %2, %3;" : "=l"(d) : "l"(a), "l"(b), "l"(c)); return d;
}
__device__ __forceinline__ u64 fadd2(u64 a, u64 b) {
    u64 d; asm("add.rn.f32x2 %0, %1, %2;" : "=l"(d) : "l"(a), "l"(b)); return d;
}
__device__ __forceinline__ u64 pack2(float lo, float hi) {
    u64 d; asm("mov.b64 %0, {%1, %2};" : "=l"(d) : "f"(lo), "f"(hi)); return d;
}
__device__ __forceinline__ float2 unpack2(u64 v) {
    float lo, hi; asm("mov.b64 {%0, %1}, %2;" : "=f"(lo), "=f"(hi) : "l"(v));
    return make_float2(lo, hi);
}
__device__ __forceinline__ u64 abs2(u64 v) {
    u64 d; asm("and.b64 %0, %1, 0x7FFFFFFF7FFFFFFF;" : "=l"(d) : "l"(v)); return d;
}
// relu2x: returns 2*relu per lane (q + |q|)
__device__ __forceinline__ u64 relu2x(u64 q) { return fadd2(q, abs2(q)); }

// ---------------- device scratch (static, allocation-free) ----------------
__device__ float g_P [H * D];   // Wo @ Wp
__device__ float g_T2[H * D];   // Wv @ P
__device__ float g_M [H * D];   // W2 @ T2
__device__ float g_c [D];       // folded bias chain
__device__ float g_sum  [H];    // per-column sum of r = 2h
__device__ float g_sumsq[H];    // per-column sum of r^2 = 4h^2
__device__ float g_Ms[H * D];   // 0.25 * diag(s) @ M
__device__ float g_c8[D];       // 0.5 * (t @ M + c)

// ---------------- fold kernels (tiny, R4-proven) ----------------
__global__ void k_fold1(const float* __restrict__ Wo, const float* __restrict__ Wp) {
    int t = blockIdx.x * blockDim.x + threadIdx.x;   // 0..2047
    int i = t >> 3, d = t & 7;
    float acc = 0.f;
#pragma unroll 8
    for (int k = 0; k < H; k++) acc = fmaf(Wo[i * H + k], Wp[k * D + d], acc);
    g_P[i * D + d] = acc;
    if (t < H) { g_sum[t] = 0.f; g_sumsq[t] = 0.f; }
}

__global__ void k_fold2(const float* __restrict__ Wv) {
    int t = blockIdx.x * blockDim.x + threadIdx.x;
    int i = t >> 3, d = t & 7;
    float acc = 0.f;
#pragma unroll 8
    for (int k = 0; k < H; k++) acc = fmaf(Wv[i * H + k], g_P[k * D + d], acc);
    g_T2[i * D + d] = acc;
}

__global__ void k_fold3(const float* __restrict__ W2, const float* __restrict__ b2,
                        const float* __restrict__ bv, const float* __restrict__ bo,
                        const float* __restrict__ bp, const float* __restrict__ Wp) {
    int t = blockIdx.x * blockDim.x + threadIdx.x;
    int i = t >> 3, d = t & 7;
    float acc = 0.f;
#pragma unroll 8
    for (int k = 0; k < H; k++) acc = fmaf(W2[i * H + k], g_T2[k * D + d], acc);
    g_M[i * D + d] = acc;
    if (t < D) {
        float c = bp[t];
        for (int k = 0; k < H; k++) {
            c = fmaf(b2[k], g_T2[k * D + t], c);
            c = fmaf(bv[k], g_P [k * D + t], c);
            c = fmaf(bo[k], Wp  [k * D + t], c);
        }
        g_c[t] = c;
    }
}

// ---------------- pass 1: batch statistics of h = relu(nc@W1 + b1) ----------------
// R4-proven: column-owner; 4 edges per iter (one LDS.128 per k); 256 threads.
__global__ void __launch_bounds__(256) k_pass1(
    const float* __restrict__ nf, const int* __restrict__ ei,
    const float* __restrict__ W1, const float* __restrict__ b1, int E) {
    __shared__ __align__(16) float ncsT[8][256];     // [k][edge-in-tile]
    const int t = threadIdx.x;

    u64 w2[8];
#pragma unroll
    for (int k = 0; k < 8; k++) { float w = W1[k * H + t]; w2[k] = pack2(w, w); }
    const float bb = b1[t];
    const u64 b2p = pack2(bb, bb);

    u64 sumA = pack2(0.f, 0.f), ssqA = sumA, sumB = sumA, ssqB = sumA;
    const int numTiles = (E + 255) >> 8;

    for (int tile = blockIdx.x; tile < numTiles; tile += gridDim.x) {
        const int base = tile << 8;
        const int cnt  = min(256, E - base);
        __syncthreads();                      // protect ncsT from prior readers
        if (t < cnt) {
            const int e  = base + t;
            const int s0 = ei[e];
            const int s1 = ei[E + e];
            const float4* a = (const float4*)(nf + (size_t)s0 * D);
            const float4* b = (const float4*)(nf + (size_t)s1 * D);
            float4 x0 = a[0], x1 = a[1], y0 = b[0], y1 = b[1];
            ncsT[0][t] = 0.5f * (x0.x + y0.x);
            ncsT[1][t] = 0.5f * (x0.y + y0.y);
            ncsT[2][t] = 0.5f * (x0.z + y0.z);
            ncsT[3][t] = 0.5f * (x0.w + y0.w);
            ncsT[4][t] = 0.5f * (x1.x + y1.x);
            ncsT[5][t] = 0.5f * (x1.y + y1.y);
            ncsT[6][t] = 0.5f * (x1.z + y1.z);
            ncsT[7][t] = 0.5f * (x1.w + y1.w);
        }
        __syncthreads();
        int e = 0;
        for (; e + 3 < cnt; e += 4) {          // 4 edges: one LDS.128 per k
            u64 q0 = b2p, q1 = b2p;
#pragma unroll
            for (int k = 0; k < 8; k++) {
                ulonglong2 n = *(const ulonglong2*)&ncsT[k][e];
                q0 = ffma2(n.x, w2[k], q0);
                q1 = ffma2(n.y, w2[k], q1);
            }
            u64 r0 = relu2x(q0);
            u64 r1 = relu2x(q1);
            sumA = fadd2(sumA, r0);      sumB = fadd2(sumB, r1);
            ssqA = ffma2(r0, r0, ssqA);  ssqB = ffma2(r1, r1, ssqB);
        }
        for (; e + 1 < cnt; e += 2) {
            u64 q0 = b2p;
#pragma unroll
            for (int k = 0; k < 8; k++)
                q0 = ffma2(*(const u64*)&ncsT[k][e], w2[k], q0);
            u64 r0 = relu2x(q0);
            sumA = fadd2(sumA, r0);
            ssqA = ffma2(r0, r0, ssqA);
        }
        if (e < cnt) {                        // odd tail: hi lane poisoned -> r=0
            u64 q0 = pack2(bb, -1e30f);
#pragma unroll
            for (int k = 0; k < 8; k++)
                q0 = ffma2(pack2(ncsT[k][e], 0.f), w2[k], q0);
            u64 r0 = relu2x(q0);
            sumA = fadd2(sumA, r0);
            ssqA = ffma2(r0, r0, ssqA);
        }
    }
    float2 sa = unpack2(fadd2(sumA, sumB));
    float2 qa = unpack2(fadd2(ssqA, ssqB));
    atomicAdd(&g_sum[t],   sa.x + sa.y);      // Σ r  (r = 2h)
    atomicAdd(&g_sumsq[t], qa.x + qa.y);      // Σ r²
}

// ---------------- finalize: fold BN affine (+relu-doubling factors) into M ----------------
__global__ void k_finalize(const float* __restrict__ gamma,
                           const float* __restrict__ beta, float invE) {
    __shared__ float tvs[H];
    const int j = threadIdx.x;
    float mu  = 0.5f  * g_sum[j]   * invE;              // E[h]
    float eh2 = 0.25f * g_sumsq[j] * invE;              // E[h^2]
    float var = fmaf(-mu, mu, eh2);                     // biased var
    float s   = gamma[j] * rsqrtf(var + BN_EPS);
    float tv  = fmaf(-mu, s, beta[j]);
#pragma unroll
    for (int d = 0; d < D; d++) g_Ms[j * D + d] = 0.25f * s * g_M[j * D + d];
    tvs[j] = tv;
    __syncthreads();
    if (j < D) {
        float acc = g_c[j];
        for (int k = 0; k < H; k++) acc = fmaf(tvs[k], g_M[k * D + j], acc);
        g_c8[j] = 0.5f * acc;
    }
}

// ---------------- pass 2: out = ea + (r @ Ms025) + c8h,  r = 2*relu(nc@W1+b1) ----------------
// R5-proven: edge-owner, 3 edges/thread, 128-thread blocks; cols packed in f32x2 pairs.
__global__ void __launch_bounds__(128) k_pass2(
    const float* __restrict__ ea, const float* __restrict__ nf,
    const int* __restrict__ ei,
    const float* __restrict__ W1, const float* __restrict__ b1,
    float* __restrict__ out, int E) {
    __shared__ __align__(16) u64 w2p [128 * 8];   // [jp][k]  = (W1[k][2jp], W1[k][2jp+1])
    __shared__ __align__(16) u64 ms2p[128 * 8];   // [jp][d]  = (Ms[2jp][d], Ms[2jp+1][d])
    __shared__ u64 b2ps[128];                     // (b1[2jp], b1[2jp+1])
    __shared__ float c8s[D];

    const int t = threadIdx.x;
    for (int idx = t; idx < 128 * 8; idx += 128) {
        int jp = idx >> 3, k = idx & 7;
        w2p [idx] = pack2(W1[k * H + 2 * jp], W1[k * H + 2 * jp + 1]);
        ms2p[idx] = pack2(g_Ms[(2 * jp) * D + k], g_Ms[(2 * jp + 1) * D + k]);
    }
    b2ps[t] = pack2(b1[2 * t], b1[2 * t + 1]);
    if (t < D) c8s[t] = g_c8[t];
    __syncthreads();

    int eidx[3]; bool val[3];
#pragma unroll
    for (int i = 0; i < 3; i++) {
        int er = blockIdx.x * 384 + i * 128 + t;
        val[i]  = er < E;
        eidx[i] = val[i] ? er : E - 1;
    }

    // gather + duplicate-pack nc for 3 edges
    u64 nc[3][8];
#pragma unroll
    for (int i = 0; i < 3; i++) {
        const int s0 = ei[eidx[i]];
        const int s1 = ei[E + eidx[i]];
        const float4* p0 = (const float4*)(nf + (size_t)s0 * D);
        const float4* p1 = (const float4*)(nf + (size_t)s1 * D);
        float4 x0 = p0[0], x1 = p0[1], y0 = p1[0], y1 = p1[1];
        float n[8];
        n[0] = 0.5f * (x0.x + y0.x); n[1] = 0.5f * (x0.y + y0.y);
        n[2] = 0.5f * (x0.z + y0.z); n[3] = 0.5f * (x0.w + y0.w);
        n[4] = 0.5f * (x1.x + y1.x); n[5] = 0.5f * (x1.y + y1.y);
        n[6] = 0.5f * (x1.z + y1.z); n[7] = 0.5f * (x1.w + y1.w);
#pragma unroll
        for (int k = 0; k < 8; k++) nc[i][k] = pack2(n[k], n[k]);
    }

    u64 acc[3][8];
    const u64 z = pack2(0.f, 0.f);
#pragma unroll
    for (int i = 0; i < 3; i++)
#pragma unroll
        for (int d = 0; d < 8; d++) acc[i][d] = z;

#pragma unroll 1
    for (int jp = 0; jp < 128; jp++) {
        u64 w8[8];
        {
            ulonglong2 v0 = *(const ulonglong2*)&w2p[jp * 8 + 0];
            ulonglong2 v1 = *(const ulonglong2*)&w2p[jp * 8 + 2];
            ulonglong2 v2 = *(const ulonglong2*)&w2p[jp * 8 + 4];
            ulonglong2 v3 = *(const ulonglong2*)&w2p[jp * 8 + 6];
            w8[0] = v0.x; w8[1] = v0.y; w8[2] = v1.x; w8[3] = v1.y;
            w8[4] = v2.x; w8[5] = v2.y; w8[6] = v3.x; w8[7] = v3.y;
        }
        const u64 bp = b2ps[jp];
        u64 q0 = bp, q1 = bp, q2 = bp;
#pragma unroll
        for (int k = 0; k < 8; k++) {
            q0 = ffma2(nc[0][k], w8[k], q0);
            q1 = ffma2(nc[1][k], w8[k], q1);
            q2 = ffma2(nc[2][k], w8[k], q2);
        }
        u64 r0 = relu2x(q0), r1 = relu2x(q1), r2 = relu2x(q2);

        u64 m8[8];
        {
            ulonglong2 v0 = *(const ulonglong2*)&ms2p[jp * 8 + 0];
            ulonglong2 v1 = *(const ulonglong2*)&ms2p[jp * 8 + 2];
            ulonglong2 v2 = *(const ulonglong2*)&ms2p[jp * 8 + 4];
            ulonglong2 v3 = *(const ulonglong2*)&ms2p[jp * 8 + 6];
            m8[0] = v0.x; m8[1] = v0.y; m8[2] = v1.x; m8[3] = v1.y;
            m8[4] = v2.x; m8[5] = v2.y; m8[6] = v3.x; m8[7] = v3.y;
        }
#pragma unroll
        for (int d = 0; d < 8; d++) {
            acc[0][d] = ffma2(r0, m8[d], acc[0][d]);
            acc[1][d] = ffma2(r1, m8[d], acc[1][d]);
            acc[2][d] = ffma2(r2, m8[d], acc[2][d]);
        }
    }

#pragma unroll
    for (int i = 0; i < 3; i++) {
        if (!val[i]) continue;
        const float4* eap = (const float4*)(ea + (size_t)eidx[i] * D);
        float4 i0 = eap[0], i1 = eap[1];
        float o[8];
#pragma unroll
        for (int d = 0; d < 8; d++) {
            float2 p = unpack2(acc[i][d]);
            o[d] = p.x + p.y + c8s[d];
        }
        float4 o0 = make_float4(i0.x + o[0], i0.y + o[1], i0.z + o[2], i0.w + o[3]);
        float4 o1 = make_float4(i1.x + o[4], i1.y + o[5], i1.z + o[6], i1.w + o[7]);
        float4* op = (float4*)(out + (size_t)eidx[i] * D);
        op[0] = o0; op[1] = o1;
    }
}

// ---------------- launcher ----------------
extern "C" void kernel_launch(void* const* d_in, const int* in_sizes, int n_in,
                              void* d_out, int out_size) {
    const float* edge_attr     = (const float*)d_in[0];
    const float* node_features = (const float*)d_in[1];
    const int*   edge_index    = (const int*)  d_in[2];
    // d_in[3..8]: edge-encoder params — unused by the reference output
    const float* n_W1    = (const float*)d_in[9];
    const float* n_b1    = (const float*)d_in[10];
    const float* n_gamma = (const float*)d_in[11];
    const float* n_beta  = (const float*)d_in[12];
    const float* n_W2    = (const float*)d_in[13];
    const float* n_b2    = (const float*)d_in[14];
    const float* Wv      = (const float*)d_in[15];
    const float* bv      = (const float*)d_in[16];
    const float* Wo      = (const float*)d_in[17];
    const float* bo      = (const float*)d_in[18];
    const float* Wp      = (const float*)d_in[19];
    const float* bp      = (const float*)d_in[20];

    const int E = in_sizes[0] / D;
    float* out = (float*)d_out;

    k_fold1<<<16, 128>>>(Wo, Wp);
    k_fold2<<<16, 128>>>(Wv);
    k_fold3<<<16, 128>>>(n_W2, n_b2, bv, bo, bp, Wp);
    k_pass1<<<1184, 256>>>(node_features, edge_index, n_W1, n_b1, E);
    k_finalize<<<1, 256>>>(n_gamma, n_beta, 1.0f / (float)E);
    k_pass2<<<(E + 383) / 384, 128>>>(edge_attr, node_features, edge_index,
                                      n_W1, n_b1, out, E);
}